// round 2
// baseline (speedup 1.0000x reference)
#include <cuda_runtime.h>
#include <math.h>

// Problem constants (fixed by setup_inputs)
#define NDIM 4096
#define BDIM 512
#define B2DIM 1024
#define EPSV   1.0f
#define LAMDA 10.0f

// ---------------- scratch (static device globals; no allocation) -------------
__device__ float g_B2 [NDIM * B2DIM];   // columns [0,512): f   | [512,1024): f*flog
__device__ float g_C  [NDIM * B2DIM];   // columns [0,512): Kf  | [512,1024): K@(f*flog)
__device__ float g_a  [NDIM * BDIM];    // a = P / Kf
__device__ float g_KTa[NDIM * BDIM];    // K^T @ a
__device__ float g_p1[NDIM], g_p2[NDIM], g_p3[NDIM], g_p4[NDIM];  // block partials

// ---------------- prep: f and f*flog from U ---------------------------------
__global__ void __launch_bounds__(512) prep_kernel(const float* __restrict__ U) {
    int i = blockIdx.x, j = threadIdx.x;
    float u    = U[i * BDIM + j];
    float flog = (LAMDA / EPSV) * logf(LAMDA / (LAMDA - u));
    float f    = expf(flog);
    g_B2[i * B2DIM + j]        = f;
    g_B2[i * B2DIM + BDIM + j] = f * flog;
}

// ---------------- SGEMM: C[M,N] = op(A)[M,K] @ B[K,N] ------------------------
// TRANSA=false: A row-major [M,lda], op(A)=A.   TRANSA=true: op(A)=A^T, A is [K,lda].
constexpr int BM = 128, BN = 128, BK = 8, TM = 8, TN = 8;  // 256 threads

template <bool TRANSA>
__global__ void __launch_bounds__(256)
sgemm_kernel(const float* __restrict__ A, const float* __restrict__ B,
             float* __restrict__ C, int M, int N, int K, int lda) {
    __shared__ float As[BK][BM];
    __shared__ float Bs[BK][BN];

    const int tid = threadIdx.x;
    const int bm  = blockIdx.y * BM;
    const int bn  = blockIdx.x * BN;
    const int tr  = (tid / 16) * TM;
    const int tc  = (tid % 16) * TN;

    float acc[TM][TN];
#pragma unroll
    for (int i = 0; i < TM; i++)
#pragma unroll
        for (int j = 0; j < TN; j++) acc[i][j] = 0.0f;

    float ar[TM], br[TN];

    for (int k0 = 0; k0 < K; k0 += BK) {
        if (!TRANSA) {
            // load A[bm + tid/2][k0 + (tid&1)*4 .. +3], store transposed
            int row = bm + (tid >> 1);
            int kk  = (tid & 1) * 4;
            float4 v = *reinterpret_cast<const float4*>(A + (long)row * lda + k0 + kk);
            As[kk + 0][tid >> 1] = v.x;
            As[kk + 1][tid >> 1] = v.y;
            As[kk + 2][tid >> 1] = v.z;
            As[kk + 3][tid >> 1] = v.w;
        } else {
            // load A[k0 + tid/32][bm + (tid&31)*4 .. +3] directly
            int row = k0 + (tid >> 5);
            int col = bm + (tid & 31) * 4;
            float4 v = *reinterpret_cast<const float4*>(A + (long)row * lda + col);
            *reinterpret_cast<float4*>(&As[tid >> 5][(tid & 31) * 4]) = v;
        }
        {
            int row = k0 + (tid >> 5);
            int col = bn + (tid & 31) * 4;
            float4 v = *reinterpret_cast<const float4*>(B + (long)row * N + col);
            *reinterpret_cast<float4*>(&Bs[tid >> 5][(tid & 31) * 4]) = v;
        }
        __syncthreads();

#pragma unroll
        for (int kk = 0; kk < BK; kk++) {
#pragma unroll
            for (int i = 0; i < TM; i++) ar[i] = As[kk][tr + i];
#pragma unroll
            for (int j = 0; j < TN; j++) br[j] = Bs[kk][tc + j];
#pragma unroll
            for (int i = 0; i < TM; i++)
#pragma unroll
                for (int j = 0; j < TN; j++) acc[i][j] = fmaf(ar[i], br[j], acc[i][j]);
        }
        __syncthreads();
    }

#pragma unroll
    for (int i = 0; i < TM; i++)
#pragma unroll
        for (int j = 0; j < TN; j += 4) {
            float4 v = make_float4(acc[i][j], acc[i][j + 1], acc[i][j + 2], acc[i][j + 3]);
            *reinterpret_cast<float4*>(C + (long)(bm + tr + i) * N + bn + tc + j) = v;
        }
}

// ---------------- block reductions -------------------------------------------
__device__ __forceinline__ float warp_sum(float v) {
#pragma unroll
    for (int o = 16; o > 0; o >>= 1) v += __shfl_down_sync(0xffffffffu, v, o);
    return v;
}

// ---------------- epilogue 1: a, S1, S2, S3 ----------------------------------
__global__ void __launch_bounds__(512) epi1_kernel(const float* __restrict__ P) {
    __shared__ float sh1[16], sh2[16], sh3[16];
    int i = blockIdx.x, j = threadIdx.x;
    float kf = g_C[i * B2DIM + j];
    float g  = g_C[i * B2DIM + BDIM + j];
    float p  = P[i * BDIM + j];
    float a  = p / kf;
    g_a[i * BDIM + j] = a;

    float s1 = a * g;                        // a * (K @ (f*flog))
    float s2 = p * (logf(p) - logf(kf));     // P * log(P/Kf)
    float s3 = p;                            // P

    s1 = warp_sum(s1); s2 = warp_sum(s2); s3 = warp_sum(s3);
    int lane = j & 31, w = j >> 5;
    if (lane == 0) { sh1[w] = s1; sh2[w] = s2; sh3[w] = s3; }
    __syncthreads();
    if (w == 0) {
        float v1 = (lane < 16) ? sh1[lane] : 0.0f;
        float v2 = (lane < 16) ? sh2[lane] : 0.0f;
        float v3 = (lane < 16) ? sh3[lane] : 0.0f;
        v1 = warp_sum(v1); v2 = warp_sum(v2); v3 = warp_sum(v3);
        if (lane == 0) { g_p1[i] = v1; g_p2[i] = v2; g_p3[i] = v3; }
    }
}

// ---------------- epilogue 2: S4 = sum f*(K^T a)*(eps*flog + lamda) ----------
__global__ void __launch_bounds__(512) epi2_kernel(const float* __restrict__ U) {
    __shared__ float sh[16];
    int i = blockIdx.x, j = threadIdx.x;
    float kta  = g_KTa[i * BDIM + j];
    float u    = U[i * BDIM + j];
    float flog = (LAMDA / EPSV) * logf(LAMDA / (LAMDA - u));
    float f    = expf(flog);
    float s4   = f * kta * (EPSV * flog + LAMDA);

    s4 = warp_sum(s4);
    int lane = j & 31, w = j >> 5;
    if (lane == 0) sh[w] = s4;
    __syncthreads();
    if (w == 0) {
        float v = (lane < 16) ? sh[lane] : 0.0f;
        v = warp_sum(v);
        if (lane == 0) g_p4[i] = v;
    }
}

// ---------------- final combine ----------------------------------------------
__global__ void __launch_bounds__(1024) final_kernel(float* __restrict__ out) {
    __shared__ float sh1[32], sh2[32], sh3[32], sh4[32];
    float s1 = 0, s2 = 0, s3 = 0, s4 = 0;
    for (int i = threadIdx.x; i < NDIM; i += blockDim.x) {
        s1 += g_p1[i]; s2 += g_p2[i]; s3 += g_p3[i]; s4 += g_p4[i];
    }
    s1 = warp_sum(s1); s2 = warp_sum(s2); s3 = warp_sum(s3); s4 = warp_sum(s4);
    int lane = threadIdx.x & 31, w = threadIdx.x >> 5;
    if (lane == 0) { sh1[w] = s1; sh2[w] = s2; sh3[w] = s3; sh4[w] = s4; }
    __syncthreads();
    if (w == 0) {
        float v1 = sh1[lane], v2 = sh2[lane], v3 = sh3[lane], v4 = sh4[lane];
        v1 = warp_sum(v1); v2 = warp_sum(v2); v3 = warp_sum(v3); v4 = warp_sum(v4);
        if (lane == 0)
            out[0] = EPSV * (v1 + v2 - v3) - v4;
    }
}

// ---------------- launch -----------------------------------------------------
extern "C" void kernel_launch(void* const* d_in, const int* in_sizes, int n_in,
                              void* d_out, int out_size) {
    const float* U = (const float*)d_in[0];
    const float* P = (const float*)d_in[1];
    const float* K = (const float*)d_in[2];
    float* out = (float*)d_out;

    float* pB2;  cudaGetSymbolAddress((void**)&pB2,  g_B2);
    float* pC;   cudaGetSymbolAddress((void**)&pC,   g_C);
    float* pa;   cudaGetSymbolAddress((void**)&pa,   g_a);
    float* pKTa; cudaGetSymbolAddress((void**)&pKTa, g_KTa);

    // 1) f, f*flog
    prep_kernel<<<NDIM, 512>>>(U);

    // 2) [Kf | K@(f*flog)] = K @ [f | f*flog]   (M=4096, N=1024, K=4096)
    {
        dim3 grid(B2DIM / BN, NDIM / BM);
        sgemm_kernel<false><<<grid, 256>>>(K, pB2, pC, NDIM, B2DIM, NDIM, NDIM);
    }

    // 3) a = P/Kf; partial sums S1,S2,S3
    epi1_kernel<<<NDIM, 512>>>(P);

    // 4) K^T @ a   (M=4096, N=512, K=4096)
    {
        dim3 grid(BDIM / BN, NDIM / BM);
        sgemm_kernel<true><<<grid, 256>>>(K, pa, pKTa, NDIM, BDIM, NDIM, NDIM);
    }

    // 5) S4 partials
    epi2_kernel<<<NDIM, 512>>>(U);

    // 6) combine
    final_kernel<<<1, 1024>>>(out);
}

// round 5
// speedup vs baseline: 3.7223x; 3.7223x over previous
#include <cuda_runtime.h>
#include <math.h>
#include <stdint.h>

#define NDIM  4096
#define BDIM  512
#define B2R   1024
#define EPSV  1.0f
#define LAMDA 10.0f

// ---------------- scratch (static device globals; no allocation) -------------
__device__ float g_B2 [NDIM * B2R ];   // [4096][1024]: cols 0..511 = f, 512..1023 = f*flog
__device__ float g_C  [NDIM * B2R ];   // [4096][1024]: cols 0..511 = Kf, 512..1023 = K@(f*flog)
__device__ float g_a  [NDIM * BDIM];   // a = P / Kf   [4096][512]
__device__ float g_KTa[NDIM * BDIM];   // K^T @ a      [4096][512]
__device__ float g_p1[NDIM], g_p2[NDIM], g_p3[NDIM], g_p4[NDIM];

// ---------------- helpers -----------------------------------------------------
__device__ __forceinline__ uint32_t smem_u32(const void* p) {
    return (uint32_t)__cvta_generic_to_shared(p);
}
__device__ __forceinline__ void cpasync16(uint32_t dst, const void* src) {
    asm volatile("cp.async.cg.shared.global [%0], [%1], 16;"
                 :: "r"(dst), "l"(src) : "memory");
}
__device__ __forceinline__ uint32_t tf32cvt(float x) {
    uint32_t r;
    asm("cvt.rna.tf32.f32 %0, %1;" : "=r"(r) : "f"(x));
    return r;
}
__device__ __forceinline__ void mma_tf32(float* c, const uint32_t* a, const uint32_t* b) {
    asm volatile(
        "mma.sync.aligned.m16n8k8.row.col.f32.tf32.tf32.f32 "
        "{%0,%1,%2,%3}, {%4,%5,%6,%7}, {%8,%9}, {%0,%1,%2,%3};"
        : "+f"(c[0]), "+f"(c[1]), "+f"(c[2]), "+f"(c[3])
        : "r"(a[0]), "r"(a[1]), "r"(a[2]), "r"(a[3]), "r"(b[0]), "r"(b[1]));
}

// ---------------- tensor-core tf32 GEMM ---------------------------------------
// C[4096, ncols] = op(K)[4096,4096] @ B[4096, ncols]
// TRANSA=false: op(K)=K (A tile stored [m][k] in smem, stride 20)
// TRANSA=true : op(K)=K^T (A tile stored [k][m] in smem, stride 136)
// B tile stored [k][n], stride 136.
#define STAGES 3
#define BKT 16

template <bool TRANSA>
__global__ void __launch_bounds__(256, 2)
gemm_mma(const float* __restrict__ A, const float* __restrict__ B,
         float* __restrict__ C, int ncols)
{
    extern __shared__ float sm[];
    constexpr int AST = TRANSA ? 136 : 20;
    constexpr int ASZ = TRANSA ? (BKT * 136) : (128 * 20);
    constexpr int BST = 136;
    constexpr int BSZ = BKT * 136;
    constexpr int STG = ASZ + BSZ;

    const int tid  = threadIdx.x;
    const int wid  = tid >> 5, lane = tid & 31;
    const int grp  = lane >> 2, tg = lane & 3;
    const int wm   = (wid >> 2) * 64;   // warp m-offset (2 warps in m)
    const int wn   = (wid & 3) * 32;    // warp n-offset (4 warps in n)
    const int bm   = blockIdx.y * 128;
    const int bn   = blockIdx.x * 128;

    float acc[4][4][4];
#pragma unroll
    for (int i = 0; i < 4; i++)
#pragma unroll
        for (int j = 0; j < 4; j++)
#pragma unroll
            for (int k = 0; k < 4; k++) acc[i][j][k] = 0.0f;

    auto load_stage = [&](int kt, int s) {
        float* As = sm + s * STG;
        float* Bs = As + ASZ;
        const int k0 = kt * BKT;
        if (!TRANSA) {
            // A tile: 128 rows (m) x 16 cols (k); smem [m][20]
#pragma unroll
            for (int h = 0; h < 2; h++) {
                int ch = tid + h * 256;          // 0..511
                int r = ch >> 2, c = ch & 3;     // r: m-row, c: 16B chunk
                cpasync16(smem_u32(As + r * AST + c * 4),
                          A + (size_t)(bm + r) * 4096 + k0 + c * 4);
            }
        } else {
            // A tile: 16 rows (k) x 128 cols (m); smem [k][136]
#pragma unroll
            for (int h = 0; h < 2; h++) {
                int ch = tid + h * 256;
                int r = ch >> 5, c = ch & 31;
                cpasync16(smem_u32(As + r * AST + c * 4),
                          A + (size_t)(k0 + r) * 4096 + bm + c * 4);
            }
        }
        // B tile: 16 rows (k) x 128 cols (n); smem [k][136]
#pragma unroll
        for (int h = 0; h < 2; h++) {
            int ch = tid + h * 256;
            int r = ch >> 5, c = ch & 31;
            cpasync16(smem_u32(Bs + r * BST + c * 4),
                      B + (size_t)(k0 + r) * (size_t)ncols + bn + c * 4);
        }
        asm volatile("cp.async.commit_group;" ::: "memory");
    };

    const int NT = 4096 / BKT;  // 256 k-tiles

    for (int kt = 0; kt < STAGES - 1; kt++) load_stage(kt, kt);

    for (int kt = 0; kt < NT; kt++) {
        asm volatile("cp.async.wait_group %0;" :: "n"(STAGES - 2) : "memory");
        __syncthreads();

        int nx = kt + STAGES - 1;
        if (nx < NT) load_stage(nx, nx % STAGES);

        const float* As = sm + (kt % STAGES) * STG;
        const float* Bs = As + ASZ;

#pragma unroll
        for (int kk = 0; kk < BKT; kk += 8) {
            uint32_t af[4][4], bf[4][2];
#pragma unroll
            for (int mf = 0; mf < 4; mf++) {
                if (!TRANSA) {
                    const float* p = As + (wm + mf * 16 + grp) * AST + kk + tg;
                    af[mf][0] = tf32cvt(p[0]);
                    af[mf][1] = tf32cvt(p[8 * AST]);
                    af[mf][2] = tf32cvt(p[4]);
                    af[mf][3] = tf32cvt(p[8 * AST + 4]);
                } else {
                    const float* p = As + (kk + tg) * AST + wm + mf * 16 + grp;
                    af[mf][0] = tf32cvt(p[0]);
                    af[mf][1] = tf32cvt(p[8]);
                    af[mf][2] = tf32cvt(p[4 * AST]);
                    af[mf][3] = tf32cvt(p[4 * AST + 8]);
                }
            }
#pragma unroll
            for (int nf = 0; nf < 4; nf++) {
                const float* p = Bs + (kk + tg) * BST + wn + nf * 8 + grp;
                bf[nf][0] = tf32cvt(p[0]);
                bf[nf][1] = tf32cvt(p[4 * BST]);
            }
#pragma unroll
            for (int mf = 0; mf < 4; mf++)
#pragma unroll
                for (int nf = 0; nf < 4; nf++)
                    mma_tf32(acc[mf][nf], af[mf], bf[nf]);
        }
    }

    // epilogue
#pragma unroll
    for (int mf = 0; mf < 4; mf++)
#pragma unroll
        for (int nf = 0; nf < 4; nf++) {
            int row = bm + wm + mf * 16 + grp;
            int col = bn + wn + nf * 8 + 2 * tg;
            float2 v0 = make_float2(acc[mf][nf][0], acc[mf][nf][1]);
            float2 v1 = make_float2(acc[mf][nf][2], acc[mf][nf][3]);
            *reinterpret_cast<float2*>(C + (size_t)row * ncols + col) = v0;
            *reinterpret_cast<float2*>(C + (size_t)(row + 8) * ncols + col) = v1;
        }
}

// ---------------- prep: f and f*flog from U -----------------------------------
__global__ void __launch_bounds__(512) prep_kernel(const float* __restrict__ U) {
    int i = blockIdx.x, j = threadIdx.x;
    float u    = U[i * BDIM + j];
    float flog = LAMDA * logf(LAMDA / (LAMDA - u));
    float f    = expf(flog);
    g_B2[(size_t)i * B2R + j]        = f;
    g_B2[(size_t)i * B2R + BDIM + j] = f * flog;
}

// ---------------- reductions ---------------------------------------------------
__device__ __forceinline__ float warp_sum(float v) {
#pragma unroll
    for (int o = 16; o > 0; o >>= 1) v += __shfl_down_sync(0xffffffffu, v, o);
    return v;
}

// ---------------- epilogue 1: a, S1, S2, S3 ------------------------------------
__global__ void __launch_bounds__(512) epi1_kernel(const float* __restrict__ P) {
    __shared__ float sh1[16], sh2[16], sh3[16];
    int i = blockIdx.x, j = threadIdx.x;
    float kf = g_C[(size_t)i * B2R + j];
    float g  = g_C[(size_t)i * B2R + BDIM + j];
    float p  = P[(size_t)i * BDIM + j];
    float a  = p / kf;
    g_a[(size_t)i * BDIM + j] = a;

    float s1 = a * g;
    float s2 = p * (logf(p) - logf(kf));
    float s3 = p;

    s1 = warp_sum(s1); s2 = warp_sum(s2); s3 = warp_sum(s3);
    int lane = j & 31, w = j >> 5;
    if (lane == 0) { sh1[w] = s1; sh2[w] = s2; sh3[w] = s3; }
    __syncthreads();
    if (w == 0) {
        float v1 = (lane < 16) ? sh1[lane] : 0.0f;
        float v2 = (lane < 16) ? sh2[lane] : 0.0f;
        float v3 = (lane < 16) ? sh3[lane] : 0.0f;
        v1 = warp_sum(v1); v2 = warp_sum(v2); v3 = warp_sum(v3);
        if (lane == 0) { g_p1[i] = v1; g_p2[i] = v2; g_p3[i] = v3; }
    }
}

// ---------------- epilogue 2: S4 = sum f*(K^T a)*(eps*flog + lamda) ------------
__global__ void __launch_bounds__(512) epi2_kernel(const float* __restrict__ U) {
    __shared__ float sh[16];
    int i = blockIdx.x, j = threadIdx.x;
    float kta  = g_KTa[(size_t)i * BDIM + j];
    float u    = U[(size_t)i * BDIM + j];
    float flog = LAMDA * logf(LAMDA / (LAMDA - u));
    float f    = expf(flog);
    float s4   = f * kta * (EPSV * flog + LAMDA);

    s4 = warp_sum(s4);
    int lane = j & 31, w = j >> 5;
    if (lane == 0) sh[w] = s4;
    __syncthreads();
    if (w == 0) {
        float v = (lane < 16) ? sh[lane] : 0.0f;
        v = warp_sum(v);
        if (lane == 0) g_p4[i] = v;
    }
}

// ---------------- final combine ------------------------------------------------
__global__ void __launch_bounds__(1024) final_kernel(float* __restrict__ out) {
    __shared__ float sh1[32], sh2[32], sh3[32], sh4[32];
    int t = threadIdx.x;
    float s1 = 0, s2 = 0, s3 = 0, s4 = 0;
    for (int i = t; i < NDIM; i += 1024) {
        s1 += g_p1[i]; s2 += g_p2[i]; s3 += g_p3[i]; s4 += g_p4[i];
    }
    s1 = warp_sum(s1); s2 = warp_sum(s2); s3 = warp_sum(s3); s4 = warp_sum(s4);
    int lane = t & 31, w = t >> 5;
    if (lane == 0) { sh1[w] = s1; sh2[w] = s2; sh3[w] = s3; sh4[w] = s4; }
    __syncthreads();
    if (w == 0) {
        float v1 = sh1[lane], v2 = sh2[lane], v3 = sh3[lane], v4 = sh4[lane];
        v1 = warp_sum(v1); v2 = warp_sum(v2); v3 = warp_sum(v3); v4 = warp_sum(v4);
        if (lane == 0) out[0] = EPSV * (v1 + v2 - v3) - v4;
    }
}

// ---------------- launch -------------------------------------------------------
extern "C" void kernel_launch(void* const* d_in, const int* in_sizes, int n_in,
                              void* d_out, int out_size) {
    const float* U = (const float*)d_in[0];
    const float* P = (const float*)d_in[1];
    const float* K = (const float*)d_in[2];
    float* out = (float*)d_out;

    float *pB2, *pC, *pa, *pKTa;
    cudaGetSymbolAddress((void**)&pB2,  g_B2);
    cudaGetSymbolAddress((void**)&pC,   g_C);
    cudaGetSymbolAddress((void**)&pa,   g_a);
    cudaGetSymbolAddress((void**)&pKTa, g_KTa);

    constexpr int SMEM_F = STAGES * (128 * 20 + BKT * 136) * 4;  // 56832 B
    constexpr int SMEM_T = STAGES * (BKT * 136 * 2) * 4;         // 52224 B
    cudaFuncSetAttribute(gemm_mma<false>,
                         cudaFuncAttributeMaxDynamicSharedMemorySize, SMEM_F);
    cudaFuncSetAttribute(gemm_mma<true>,
                         cudaFuncAttributeMaxDynamicSharedMemorySize, SMEM_T);

    // 1) f, f*flog
    prep_kernel<<<NDIM, 512>>>(U);
    // 2) [Kf | K@(f*flog)] = K @ [f | f*flog]
    gemm_mma<false><<<dim3(B2R / 128, NDIM / 128), 256, SMEM_F>>>(K, pB2, pC, B2R);
    // 3) a = P/Kf + partials
    epi1_kernel<<<NDIM, 512>>>(P);
    // 4) K^T @ a
    gemm_mma<true><<<dim3(BDIM / 128, NDIM / 128), 256, SMEM_T>>>(K, pa, pKTa, BDIM);
    // 5) S4 partials
    epi2_kernel<<<NDIM, 512>>>(U);
    // 6) combine
    final_kernel<<<1, 1024>>>(out);
}